// round 1
// baseline (speedup 1.0000x reference)
#include <cuda_runtime.h>
#include <math.h>

#define N_TOK 1024
#define Dm 512
#define Kf 128
#define Sq 512
#define Hh 8
#define DK 64

// ---------------- scratch (device globals; no allocation allowed) -----------
__device__ float g_xf[N_TOK * Kf];
__device__ float g_pf[4][Dm * Kf];
__device__ float g_Q[N_TOK * Dm];
__device__ float g_Kb[N_TOK * Dm];
__device__ float g_V[N_TOK * Dm];
__device__ float g_scores[16 * Sq * Sq];
__device__ float g_ctx[N_TOK * Dm];
__device__ float g_cf[N_TOK * Kf];

// ---------------- generic fp32 tiled GEMM: C = A(MxK) @ B(KxN) --------------
// M%64==0, N%64==0, K%32==0. Row-major with leading dims.
__global__ __launch_bounds__(256) void gemm_nn(
    const float* __restrict__ A, const float* __restrict__ B,
    float* __restrict__ C, int M, int N, int K, int lda, int ldb, int ldc)
{
    __shared__ float As[32][68];
    __shared__ float Bs[32][68];
    int tx = threadIdx.x, ty = threadIdx.y;
    int tid = ty * 16 + tx;
    int bm = blockIdx.y * 64, bn = blockIdx.x * 64;
    float acc[4][4] = {};
    for (int k0 = 0; k0 < K; k0 += 32) {
#pragma unroll
        for (int l = 0; l < 8; l++) {        // A tile 64x32 -> As[k][m]
            int e = tid + l * 256;
            int i = e >> 5, j = e & 31;
            As[j][i] = A[(size_t)(bm + i) * lda + k0 + j];
        }
#pragma unroll
        for (int l = 0; l < 8; l++) {        // B tile 32x64 -> Bs[k][n]
            int e = tid + l * 256;
            int kk = e >> 6, j = e & 63;
            Bs[kk][j] = B[(size_t)(k0 + kk) * ldb + bn + j];
        }
        __syncthreads();
#pragma unroll
        for (int k = 0; k < 32; k++) {
            float4 a4 = *(const float4*)&As[k][ty * 4];
            float4 b4 = *(const float4*)&Bs[k][tx * 4];
            float av[4] = {a4.x, a4.y, a4.z, a4.w};
            float bv[4] = {b4.x, b4.y, b4.z, b4.w};
#pragma unroll
            for (int i = 0; i < 4; i++)
#pragma unroll
                for (int j = 0; j < 4; j++)
                    acc[i][j] = fmaf(av[i], bv[j], acc[i][j]);
        }
        __syncthreads();
    }
#pragma unroll
    for (int i = 0; i < 4; i++)
#pragma unroll
        for (int j = 0; j < 4; j++)
            C[(size_t)(bm + ty * 4 + i) * ldc + bn + tx * 4 + j] = acc[i][j];
}

// ---------------- Tversky similarity: out[n][o], n-tile 64 x o-tile 64 ------
// sim = theta*sum(max(a,0)*max(p,0))
//     - alpha*sum_{a>0} relu(a-p)
//     - beta *sum_{p>0} relu(p-a)
// Inner loop per (pair,k): 6 fp ops using relu(p-a) = relu(a-p) - (a-p).
__global__ __launch_bounds__(256) void tversky_kernel(
    const float* __restrict__ xf, const float* __restrict__ pf,
    const float* __restrict__ tab, float* __restrict__ out, int ldo)
{
    __shared__ float sxa[16][68], sxp[16][68], sxm[16][68];
    __shared__ float spa[16][68], spt[16][68], spb[16][68];
    const float th = tab[0], al = tab[1], be = tab[2];
    int tx = threadIdx.x, ty = threadIdx.y;
    int tid = ty * 16 + tx;
    int bo = blockIdx.x * 64;
    int bn = blockIdx.y * 64;
    float acc[4][4] = {};
    for (int k0 = 0; k0 < Kf; k0 += 16) {
#pragma unroll
        for (int l = 0; l < 4; l++) {
            int e = tid + l * 256;
            int i = e >> 4, j = e & 15;
            float a = xf[(size_t)(bn + i) * Kf + k0 + j];
            sxa[j][i] = a;
            sxp[j][i] = fmaxf(a, 0.f);
            sxm[j][i] = (a > 0.f) ? -al : 0.f;
            float p = pf[(size_t)(bo + i) * Kf + k0 + j];
            spa[j][i] = p;
            spt[j][i] = th * fmaxf(p, 0.f);
            spb[j][i] = (p > 0.f) ? -be : 0.f;
        }
        __syncthreads();
#pragma unroll
        for (int k = 0; k < 16; k++) {
            float4 a4  = *(const float4*)&sxa[k][ty * 4];
            float4 ap4 = *(const float4*)&sxp[k][ty * 4];
            float4 am4 = *(const float4*)&sxm[k][ty * 4];
            float4 p4  = *(const float4*)&spa[k][tx * 4];
            float4 tp4 = *(const float4*)&spt[k][tx * 4];
            float4 pb4 = *(const float4*)&spb[k][tx * 4];
            float av[4]  = {a4.x, a4.y, a4.z, a4.w};
            float apv[4] = {ap4.x, ap4.y, ap4.z, ap4.w};
            float amv[4] = {am4.x, am4.y, am4.z, am4.w};
            float pv[4]  = {p4.x, p4.y, p4.z, p4.w};
            float tpv[4] = {tp4.x, tp4.y, tp4.z, tp4.w};
            float pbv[4] = {pb4.x, pb4.y, pb4.z, pb4.w};
#pragma unroll
            for (int i = 0; i < 4; i++)
#pragma unroll
                for (int j = 0; j < 4; j++) {
                    float d   = av[i] - pv[j];
                    float dab = fmaxf(d, 0.f);
                    float dba = dab - d;
                    float t = acc[i][j];
                    t = fmaf(apv[i], tpv[j], t);
                    t = fmaf(amv[i], dab, t);
                    t = fmaf(pbv[j], dba, t);
                    acc[i][j] = t;
                }
        }
        __syncthreads();
    }
#pragma unroll
    for (int i = 0; i < 4; i++)
#pragma unroll
        for (int j = 0; j < 4; j++)
            out[(size_t)(bn + ty * 4 + i) * ldo + bo + tx * 4 + j] = acc[i][j];
}

// ---------------- attention scores: S = Q @ K^T * 1/8, masked ---------------
__global__ __launch_bounds__(256) void scores_kernel(
    const float* __restrict__ Q, const float* __restrict__ Km,
    const int* __restrict__ mask, float* __restrict__ scores)
{
    __shared__ float Qs[64][68];   // [d][m]
    __shared__ float Ks[64][68];
    int z = blockIdx.z;
    int b = z >> 3, h = z & 7;
    const float* Qg = Q  + (size_t)b * Sq * Dm + h * DK;
    const float* Kg = Km + (size_t)b * Sq * Dm + h * DK;
    int bq = blockIdx.y * 64, bk = blockIdx.x * 64;
    int tx = threadIdx.x, ty = threadIdx.y;
    int tid = ty * 16 + tx;
#pragma unroll
    for (int l = 0; l < 16; l++) {
        int e = tid + l * 256;
        int m = e >> 6, d = e & 63;
        Qs[d][m] = Qg[(size_t)(bq + m) * Dm + d];
        Ks[d][m] = Kg[(size_t)(bk + m) * Dm + d];
    }
    __syncthreads();
    float acc[4][4] = {};
#pragma unroll
    for (int d = 0; d < 64; d++) {
        float4 a4 = *(const float4*)&Qs[d][ty * 4];
        float4 b4 = *(const float4*)&Ks[d][tx * 4];
        float av[4] = {a4.x, a4.y, a4.z, a4.w};
        float bv[4] = {b4.x, b4.y, b4.z, b4.w};
#pragma unroll
        for (int i = 0; i < 4; i++)
#pragma unroll
            for (int j = 0; j < 4; j++)
                acc[i][j] = fmaf(av[i], bv[j], acc[i][j]);
    }
    float* sout = scores + (size_t)z * Sq * Sq;
    const int* mg = mask + (size_t)b * Sq * Sq;
#pragma unroll
    for (int i = 0; i < 4; i++)
#pragma unroll
        for (int j = 0; j < 4; j++) {
            int q = bq + ty * 4 + i, kk = bk + tx * 4 + j;
            float s = acc[i][j] * 0.125f;
            if (mg[(size_t)q * Sq + kk] == 0) s = -INFINITY;
            sout[(size_t)q * Sq + kk] = s;
        }
}

// ---------------- row softmax over 512 ------------------------------------
__global__ __launch_bounds__(128) void softmax_kernel(float* __restrict__ scores)
{
    __shared__ float red_m[4], red_s[4];
    size_t row = blockIdx.x;
    float* r = scores + row * Sq;
    int t = threadIdx.x;
    float v0 = r[t], v1 = r[t + 128], v2 = r[t + 256], v3 = r[t + 384];
    float m = fmaxf(fmaxf(v0, v1), fmaxf(v2, v3));
#pragma unroll
    for (int o = 16; o; o >>= 1) m = fmaxf(m, __shfl_xor_sync(0xffffffffu, m, o));
    if ((t & 31) == 0) red_m[t >> 5] = m;
    __syncthreads();
    m = fmaxf(fmaxf(red_m[0], red_m[1]), fmaxf(red_m[2], red_m[3]));
    float e0 = expf(v0 - m), e1 = expf(v1 - m), e2 = expf(v2 - m), e3 = expf(v3 - m);
    float s = e0 + e1 + e2 + e3;
#pragma unroll
    for (int o = 16; o; o >>= 1) s += __shfl_xor_sync(0xffffffffu, s, o);
    if ((t & 31) == 0) red_s[t >> 5] = s;
    __syncthreads();
    s = red_s[0] + red_s[1] + red_s[2] + red_s[3];
    float inv = 1.f / s;
    r[t]       = e0 * inv;
    r[t + 128] = e1 * inv;
    r[t + 256] = e2 * inv;
    r[t + 384] = e3 * inv;
}

// ---------------- ctx = attn @ V (per head) --------------------------------
__global__ __launch_bounds__(256) void ctx_kernel(
    const float* __restrict__ scores, const float* __restrict__ V,
    float* __restrict__ ctx)
{
    __shared__ float As[32][68];   // [k][q]
    __shared__ float Bs[32][68];   // [k][d]
    int z = blockIdx.z;
    int b = z >> 3, h = z & 7;
    const float* Ag = scores + (size_t)z * Sq * Sq;
    const float* Vg = V + (size_t)b * Sq * Dm + h * DK;
    int bq = blockIdx.y * 64;
    int tx = threadIdx.x, ty = threadIdx.y;
    int tid = ty * 16 + tx;
    float acc[4][4] = {};
    for (int k0 = 0; k0 < Sq; k0 += 32) {
#pragma unroll
        for (int l = 0; l < 8; l++) {
            int e = tid + l * 256;
            int q = e >> 5, kk = e & 31;
            As[kk][q] = Ag[(size_t)(bq + q) * Sq + k0 + kk];
        }
#pragma unroll
        for (int l = 0; l < 8; l++) {
            int e = tid + l * 256;
            int kk = e >> 6, d = e & 63;
            Bs[kk][d] = Vg[(size_t)(k0 + kk) * Dm + d];
        }
        __syncthreads();
#pragma unroll
        for (int k = 0; k < 32; k++) {
            float4 a4 = *(const float4*)&As[k][ty * 4];
            float4 b4 = *(const float4*)&Bs[k][tx * 4];
            float av[4] = {a4.x, a4.y, a4.z, a4.w};
            float bv[4] = {b4.x, b4.y, b4.z, b4.w};
#pragma unroll
            for (int i = 0; i < 4; i++)
#pragma unroll
                for (int j = 0; j < 4; j++)
                    acc[i][j] = fmaf(av[i], bv[j], acc[i][j]);
        }
        __syncthreads();
    }
    float* cg = ctx + (size_t)b * Sq * Dm + h * DK;
#pragma unroll
    for (int i = 0; i < 4; i++)
#pragma unroll
        for (int j = 0; j < 4; j++)
            cg[(size_t)(bq + ty * 4 + i) * Dm + tx * 4 + j] = acc[i][j];
}

// ---------------- launch ----------------------------------------------------
extern "C" void kernel_launch(void* const* d_in, const int* in_sizes, int n_in,
                              void* d_out, int out_size)
{
    const float* x     = (const float*)d_in[0];
    const int*   mask  = (const int*)d_in[1];
    const float* omega = (const float*)d_in[2];
    const float* Pq    = (const float*)d_in[3];
    const float* Pk    = (const float*)d_in[4];
    const float* Pv    = (const float*)d_in[5];
    const float* Po    = (const float*)d_in[6];
    const float* tab   = (const float*)d_in[7];
    float* out = (float*)d_out;

    float *p_xf, *p_pf, *p_Q, *p_K, *p_V, *p_sc, *p_ctx, *p_cf;
    cudaGetSymbolAddress((void**)&p_xf, g_xf);
    cudaGetSymbolAddress((void**)&p_pf, g_pf);
    cudaGetSymbolAddress((void**)&p_Q, g_Q);
    cudaGetSymbolAddress((void**)&p_K, g_Kb);
    cudaGetSymbolAddress((void**)&p_V, g_V);
    cudaGetSymbolAddress((void**)&p_sc, g_scores);
    cudaGetSymbolAddress((void**)&p_ctx, g_ctx);
    cudaGetSymbolAddress((void**)&p_cf, g_cf);

    dim3 blk(16, 16);

    // feature maps
    gemm_nn<<<dim3(2, 16), blk>>>(x,  omega, p_xf, N_TOK, Kf, Dm, Dm, Kf, Kf);
    gemm_nn<<<dim3(2, 8),  blk>>>(Pq, omega, p_pf + 0 * Dm * Kf, Dm, Kf, Dm, Dm, Kf, Kf);
    gemm_nn<<<dim3(2, 8),  blk>>>(Pk, omega, p_pf + 1 * Dm * Kf, Dm, Kf, Dm, Dm, Kf, Kf);
    gemm_nn<<<dim3(2, 8),  blk>>>(Pv, omega, p_pf + 2 * Dm * Kf, Dm, Kf, Dm, Dm, Kf, Kf);
    gemm_nn<<<dim3(2, 8),  blk>>>(Po, omega, p_pf + 3 * Dm * Kf, Dm, Kf, Dm, Dm, Kf, Kf);

    // Q, K, V projections
    tversky_kernel<<<dim3(8, 16), blk>>>(p_xf, p_pf + 0 * Dm * Kf, tab + 0, p_Q, Dm);
    tversky_kernel<<<dim3(8, 16), blk>>>(p_xf, p_pf + 1 * Dm * Kf, tab + 3, p_K, Dm);
    tversky_kernel<<<dim3(8, 16), blk>>>(p_xf, p_pf + 2 * Dm * Kf, tab + 6, p_V, Dm);

    // attention
    scores_kernel<<<dim3(8, 8, 16), blk>>>(p_Q, p_K, mask, p_sc);
    softmax_kernel<<<16 * Sq, 128>>>(p_sc);
    ctx_kernel<<<dim3(1, 8, 16), blk>>>(p_sc, p_V, p_ctx);

    // output projection
    gemm_nn<<<dim3(2, 16), blk>>>(p_ctx, omega, p_cf, N_TOK, Kf, Dm, Dm, Kf, Kf);
    tversky_kernel<<<dim3(8, 16), blk>>>(p_cf, p_pf + 3 * Dm * Kf, tab + 9, out, Dm);
}

// round 2
// speedup vs baseline: 1.4336x; 1.4336x over previous
#include <cuda_runtime.h>
#include <math.h>

#define N_TOK 1024
#define Dm 512
#define Kf 128
#define Sq 512
#define DK 64

// ---------------- scratch (device globals; no allocation allowed) -----------
// g_feat: [ xf(1024x128) | pfQ(512x128) | pfK | pfV | pfO ]
__device__ float g_feat[(N_TOK + 4 * Dm) * Kf];
__device__ float g_QKV[3 * N_TOK * Dm];
__device__ float g_scores[16 * Sq * Sq];
__device__ float g_ctx[N_TOK * Dm];
__device__ float g_cf[N_TOK * Kf];

// ---------------- fused feature GEMM: feat = [x;Pq;Pk;Pv;Po] @ omega --------
// Virtual M = 3072, N = 128, K = 512. 64x64 tiles, grid (2, 48).
__global__ __launch_bounds__(256) void feat_gemm(
    const float* __restrict__ x,  const float* __restrict__ Pq,
    const float* __restrict__ Pk, const float* __restrict__ Pv,
    const float* __restrict__ Po, const float* __restrict__ omega,
    float* __restrict__ feat)
{
    __shared__ float As[32][68];
    __shared__ float Bs[32][68];
    int tx = threadIdx.x, ty = threadIdx.y;
    int tid = ty * 16 + tx;
    int bm = blockIdx.y * 64, bn = blockIdx.x * 64;

    const float* A;
    int row0;
    if (bm < N_TOK) { A = x; row0 = bm; }
    else {
        int s = (bm - N_TOK) >> 9;           // which prototype matrix
        const float* Ps[4] = {Pq, Pk, Pv, Po};
        A = Ps[s]; row0 = (bm - N_TOK) & 511;
    }

    float acc[4][4] = {};
    for (int k0 = 0; k0 < Dm; k0 += 32) {
#pragma unroll
        for (int l = 0; l < 8; l++) {        // A tile 64x32 -> As[k][m]
            int e = tid + l * 256;
            int i = e >> 5, j = e & 31;
            As[j][i] = A[(size_t)(row0 + i) * Dm + k0 + j];
        }
#pragma unroll
        for (int l = 0; l < 8; l++) {        // B tile 32x64 -> Bs[k][n]
            int e = tid + l * 256;
            int kk = e >> 6, j = e & 63;
            Bs[kk][j] = omega[(size_t)(k0 + kk) * Kf + bn + j];
        }
        __syncthreads();
#pragma unroll
        for (int k = 0; k < 32; k++) {
            float4 a4 = *(const float4*)&As[k][ty * 4];
            float4 b4 = *(const float4*)&Bs[k][tx * 4];
            float av[4] = {a4.x, a4.y, a4.z, a4.w};
            float bv[4] = {b4.x, b4.y, b4.z, b4.w};
#pragma unroll
            for (int i = 0; i < 4; i++)
#pragma unroll
                for (int j = 0; j < 4; j++)
                    acc[i][j] = fmaf(av[i], bv[j], acc[i][j]);
        }
        __syncthreads();
    }
#pragma unroll
    for (int i = 0; i < 4; i++)
#pragma unroll
        for (int j = 0; j < 4; j++)
            feat[(size_t)(bm + ty * 4 + i) * Kf + bn + tx * 4 + j] = acc[i][j];
}

// ---------------- plain GEMM for ctx @ omega --------------------------------
__global__ __launch_bounds__(256) void gemm_nn(
    const float* __restrict__ A, const float* __restrict__ B,
    float* __restrict__ C, int M, int N, int K, int lda, int ldb, int ldc)
{
    __shared__ float As[32][68];
    __shared__ float Bs[32][68];
    int tx = threadIdx.x, ty = threadIdx.y;
    int tid = ty * 16 + tx;
    int bm = blockIdx.y * 64, bn = blockIdx.x * 64;
    float acc[4][4] = {};
    for (int k0 = 0; k0 < K; k0 += 32) {
#pragma unroll
        for (int l = 0; l < 8; l++) {
            int e = tid + l * 256;
            int i = e >> 5, j = e & 31;
            As[j][i] = A[(size_t)(bm + i) * lda + k0 + j];
        }
#pragma unroll
        for (int l = 0; l < 8; l++) {
            int e = tid + l * 256;
            int kk = e >> 6, j = e & 63;
            Bs[kk][j] = B[(size_t)(k0 + kk) * ldb + bn + j];
        }
        __syncthreads();
#pragma unroll
        for (int k = 0; k < 32; k++) {
            float4 a4 = *(const float4*)&As[k][ty * 4];
            float4 b4 = *(const float4*)&Bs[k][tx * 4];
            float av[4] = {a4.x, a4.y, a4.z, a4.w};
            float bv[4] = {b4.x, b4.y, b4.z, b4.w};
#pragma unroll
            for (int i = 0; i < 4; i++)
#pragma unroll
                for (int j = 0; j < 4; j++)
                    acc[i][j] = fmaf(av[i], bv[j], acc[i][j]);
        }
        __syncthreads();
    }
#pragma unroll
    for (int i = 0; i < 4; i++)
#pragma unroll
        for (int j = 0; j < 4; j++)
            C[(size_t)(bm + ty * 4 + i) * ldc + bn + tx * 4 + j] = acc[i][j];
}

// ---------------- Tversky similarity core (device inline) -------------------
// sim = theta*sum(max(a,0)*max(p,0)) - alpha*sum_{a>0} relu(a-p)
//     - beta*sum_{p>0} relu(p-a);  relu(p-a) = relu(a-p) - (a-p).
__device__ __forceinline__ void tversky_tile(
    const float* __restrict__ xf, const float* __restrict__ pf,
    float th, float al, float be, int bn, int bo,
    float* __restrict__ out, int ldo)
{
    __shared__ float sxa[16][68], sxp[16][68], sxm[16][68];
    __shared__ float spa[16][68], spt[16][68], spb[16][68];
    int tx = threadIdx.x, ty = threadIdx.y;
    int tid = ty * 16 + tx;
    float acc[4][4] = {};
    for (int k0 = 0; k0 < Kf; k0 += 16) {
#pragma unroll
        for (int l = 0; l < 4; l++) {
            int e = tid + l * 256;
            int i = e >> 4, j = e & 15;
            float a = xf[(size_t)(bn + i) * Kf + k0 + j];
            sxa[j][i] = a;
            sxp[j][i] = fmaxf(a, 0.f);
            sxm[j][i] = (a > 0.f) ? -al : 0.f;
            float p = pf[(size_t)(bo + i) * Kf + k0 + j];
            spa[j][i] = p;
            spt[j][i] = th * fmaxf(p, 0.f);
            spb[j][i] = (p > 0.f) ? -be : 0.f;
        }
        __syncthreads();
#pragma unroll
        for (int k = 0; k < 16; k++) {
            float4 a4  = *(const float4*)&sxa[k][ty * 4];
            float4 ap4 = *(const float4*)&sxp[k][ty * 4];
            float4 am4 = *(const float4*)&sxm[k][ty * 4];
            float4 p4  = *(const float4*)&spa[k][tx * 4];
            float4 tp4 = *(const float4*)&spt[k][tx * 4];
            float4 pb4 = *(const float4*)&spb[k][tx * 4];
            float av[4]  = {a4.x, a4.y, a4.z, a4.w};
            float apv[4] = {ap4.x, ap4.y, ap4.z, ap4.w};
            float amv[4] = {am4.x, am4.y, am4.z, am4.w};
            float pv[4]  = {p4.x, p4.y, p4.z, p4.w};
            float tpv[4] = {tp4.x, tp4.y, tp4.z, tp4.w};
            float pbv[4] = {pb4.x, pb4.y, pb4.z, pb4.w};
#pragma unroll
            for (int i = 0; i < 4; i++)
#pragma unroll
                for (int j = 0; j < 4; j++) {
                    float d   = av[i] - pv[j];
                    float dab = fmaxf(d, 0.f);
                    float dba = dab - d;
                    float t = acc[i][j];
                    t = fmaf(apv[i], tpv[j], t);
                    t = fmaf(amv[i], dab, t);
                    t = fmaf(pbv[j], dba, t);
                    acc[i][j] = t;
                }
        }
        __syncthreads();
    }
#pragma unroll
    for (int i = 0; i < 4; i++)
#pragma unroll
        for (int j = 0; j < 4; j++)
            out[(size_t)(bn + ty * 4 + i) * ldo + bo + tx * 4 + j] = acc[i][j];
}

// Fused Q/K/V Tversky projections: z selects prototype seg + tab row + output.
__global__ __launch_bounds__(256) void tversky_qkv(
    const float* __restrict__ feat, const float* __restrict__ tab,
    float* __restrict__ qkv)
{
    int z = blockIdx.z;
    const float* xf = feat;
    const float* pf = feat + (size_t)(N_TOK + z * Dm) * Kf;
    const float* t3 = tab + z * 3;
    float* out = qkv + (size_t)z * N_TOK * Dm;
    tversky_tile(xf, pf, t3[0], t3[1], t3[2],
                 blockIdx.y * 64, blockIdx.x * 64, out, Dm);
}

// Output-projection Tversky.
__global__ __launch_bounds__(256) void tversky_out(
    const float* __restrict__ cf, const float* __restrict__ feat,
    const float* __restrict__ tab, float* __restrict__ out)
{
    const float* pf = feat + (size_t)(N_TOK + 3 * Dm) * Kf;
    tversky_tile(cf, pf, tab[9], tab[10], tab[11],
                 blockIdx.y * 64, blockIdx.x * 64, out, Dm);
}

// ---------------- attention scores: S = Q @ K^T * 1/8, masked ---------------
__global__ __launch_bounds__(256) void scores_kernel(
    const float* __restrict__ Q, const float* __restrict__ Km,
    const int* __restrict__ mask, float* __restrict__ scores)
{
    __shared__ float Qs[64][68];   // [d][m]
    __shared__ float Ks[64][68];
    int z = blockIdx.z;
    int b = z >> 3, h = z & 7;
    const float* Qg = Q  + (size_t)b * Sq * Dm + h * DK;
    const float* Kg = Km + (size_t)b * Sq * Dm + h * DK;
    int bq = blockIdx.y * 64, bk = blockIdx.x * 64;
    int tx = threadIdx.x, ty = threadIdx.y;
    int tid = ty * 16 + tx;
#pragma unroll
    for (int l = 0; l < 16; l++) {
        int e = tid + l * 256;
        int m = e >> 6, d = e & 63;
        Qs[d][m] = Qg[(size_t)(bq + m) * Dm + d];
        Ks[d][m] = Kg[(size_t)(bk + m) * Dm + d];
    }
    __syncthreads();
    float acc[4][4] = {};
#pragma unroll
    for (int d = 0; d < 64; d++) {
        float4 a4 = *(const float4*)&Qs[d][ty * 4];
        float4 b4 = *(const float4*)&Ks[d][tx * 4];
        float av[4] = {a4.x, a4.y, a4.z, a4.w};
        float bv[4] = {b4.x, b4.y, b4.z, b4.w};
#pragma unroll
        for (int i = 0; i < 4; i++)
#pragma unroll
            for (int j = 0; j < 4; j++)
                acc[i][j] = fmaf(av[i], bv[j], acc[i][j]);
    }
    float* sout = scores + (size_t)z * Sq * Sq;
    const int* mg = mask + (size_t)b * Sq * Sq;
#pragma unroll
    for (int i = 0; i < 4; i++)
#pragma unroll
        for (int j = 0; j < 4; j++) {
            int q = bq + ty * 4 + i, kk = bk + tx * 4 + j;
            float s = acc[i][j] * 0.125f;
            if (mg[(size_t)q * Sq + kk] == 0) s = -INFINITY;
            sout[(size_t)q * Sq + kk] = s;
        }
}

// ---------------- row softmax over 512 ------------------------------------
__global__ __launch_bounds__(128) void softmax_kernel(float* __restrict__ scores)
{
    __shared__ float red_m[4], red_s[4];
    size_t row = blockIdx.x;
    float* r = scores + row * Sq;
    int t = threadIdx.x;
    float v0 = r[t], v1 = r[t + 128], v2 = r[t + 256], v3 = r[t + 384];
    float m = fmaxf(fmaxf(v0, v1), fmaxf(v2, v3));
#pragma unroll
    for (int o = 16; o; o >>= 1) m = fmaxf(m, __shfl_xor_sync(0xffffffffu, m, o));
    if ((t & 31) == 0) red_m[t >> 5] = m;
    __syncthreads();
    m = fmaxf(fmaxf(red_m[0], red_m[1]), fmaxf(red_m[2], red_m[3]));
    float e0 = expf(v0 - m), e1 = expf(v1 - m), e2 = expf(v2 - m), e3 = expf(v3 - m);
    float s = e0 + e1 + e2 + e3;
#pragma unroll
    for (int o = 16; o; o >>= 1) s += __shfl_xor_sync(0xffffffffu, s, o);
    if ((t & 31) == 0) red_s[t >> 5] = s;
    __syncthreads();
    s = red_s[0] + red_s[1] + red_s[2] + red_s[3];
    float inv = 1.f / s;
    r[t]       = e0 * inv;
    r[t + 128] = e1 * inv;
    r[t + 256] = e2 * inv;
    r[t + 384] = e3 * inv;
}

// ---------------- ctx = attn @ V (per head) --------------------------------
__global__ __launch_bounds__(256) void ctx_kernel(
    const float* __restrict__ scores, const float* __restrict__ V,
    float* __restrict__ ctx)
{
    __shared__ float As[32][68];   // [k][q]
    __shared__ float Bs[32][68];   // [k][d]
    int z = blockIdx.z;
    int b = z >> 3, h = z & 7;
    const float* Ag = scores + (size_t)z * Sq * Sq;
    const float* Vg = V + (size_t)b * Sq * Dm + h * DK;
    int bq = blockIdx.y * 64;
    int tx = threadIdx.x, ty = threadIdx.y;
    int tid = ty * 16 + tx;
    float acc[4][4] = {};
    for (int k0 = 0; k0 < Sq; k0 += 32) {
#pragma unroll
        for (int l = 0; l < 8; l++) {
            int e = tid + l * 256;
            int q = e >> 5, kk = e & 31;
            As[kk][q] = Ag[(size_t)(bq + q) * Sq + k0 + kk];
        }
#pragma unroll
        for (int l = 0; l < 8; l++) {
            int e = tid + l * 256;
            int kk = e >> 6, d = e & 63;
            Bs[kk][d] = Vg[(size_t)(k0 + kk) * Dm + d];
        }
        __syncthreads();
#pragma unroll
        for (int k = 0; k < 32; k++) {
            float4 a4 = *(const float4*)&As[k][ty * 4];
            float4 b4 = *(const float4*)&Bs[k][tx * 4];
            float av[4] = {a4.x, a4.y, a4.z, a4.w};
            float bv[4] = {b4.x, b4.y, b4.z, b4.w};
#pragma unroll
            for (int i = 0; i < 4; i++)
#pragma unroll
                for (int j = 0; j < 4; j++)
                    acc[i][j] = fmaf(av[i], bv[j], acc[i][j]);
        }
        __syncthreads();
    }
    float* cg = ctx + (size_t)b * Sq * Dm + h * DK;
#pragma unroll
    for (int i = 0; i < 4; i++)
#pragma unroll
        for (int j = 0; j < 4; j++)
            cg[(size_t)(bq + ty * 4 + i) * Dm + tx * 4 + j] = acc[i][j];
}

// ---------------- launch ----------------------------------------------------
extern "C" void kernel_launch(void* const* d_in, const int* in_sizes, int n_in,
                              void* d_out, int out_size)
{
    const float* x     = (const float*)d_in[0];
    const int*   mask  = (const int*)d_in[1];
    const float* omega = (const float*)d_in[2];
    const float* Pq    = (const float*)d_in[3];
    const float* Pk    = (const float*)d_in[4];
    const float* Pv    = (const float*)d_in[5];
    const float* Po    = (const float*)d_in[6];
    const float* tab   = (const float*)d_in[7];
    float* out = (float*)d_out;

    float *p_feat, *p_qkv, *p_sc, *p_ctx, *p_cf;
    cudaGetSymbolAddress((void**)&p_feat, g_feat);
    cudaGetSymbolAddress((void**)&p_qkv, g_QKV);
    cudaGetSymbolAddress((void**)&p_sc, g_scores);
    cudaGetSymbolAddress((void**)&p_ctx, g_ctx);
    cudaGetSymbolAddress((void**)&p_cf, g_cf);

    float* p_Q = p_qkv;
    float* p_K = p_qkv + (size_t)N_TOK * Dm;
    float* p_V = p_qkv + (size_t)2 * N_TOK * Dm;

    dim3 blk(16, 16);

    // all 5 feature maps in one launch (M=3072, N=128, K=512)
    feat_gemm<<<dim3(2, 48), blk>>>(x, Pq, Pk, Pv, Po, omega, p_feat);

    // Q, K, V projections in one launch
    tversky_qkv<<<dim3(8, 16, 3), blk>>>(p_feat, tab, p_qkv);

    // attention
    scores_kernel<<<dim3(8, 8, 16), blk>>>(p_Q, p_K, mask, p_sc);
    softmax_kernel<<<16 * Sq, 128>>>(p_sc);
    ctx_kernel<<<dim3(1, 8, 16), blk>>>(p_sc, p_V, p_ctx);

    // output projection
    gemm_nn<<<dim3(2, 16), blk>>>(p_ctx, omega, p_cf, N_TOK, Kf, Dm, Dm, Kf, Kf);
    tversky_out<<<dim3(8, 16), blk>>>(p_cf, p_feat, tab, out);
}